// round 7
// baseline (speedup 1.0000x reference)
#include <cuda_runtime.h>
#include <cuda_fp16.h>
#include <cstdint>
#include <cstddef>

// ============================================================
// out = L1rownorm(A[8192,8192]) @ X[8192,512] @ W[512,256] + bias
//   Xh = fp16(X), Wth = fp16(W^T)
//   Yt[256,8192](fp16) = Wth @ Xh^T             (fp16 HMMA)
//   partial[ks] = A[:,ks-half] @ Y[ks-half,:]   (fp16 HMMA, tile 128x128, K-split 2)
//   out = (p0+p1) / (rs0+rs1) + bias            (reduce kernel)
// ============================================================

#define N_ROWS 8192
#define F_IN   512
#define F_OUT  256

// ---- GEMM1 (fp16, cp.async both operands) ----
#define G1_ST  (128 * 40 * 2)        // 10240 B per operand stage
#define G1_STAGE (2 * G1_ST)
#define G1_SMEM (3 * G1_STAGE)       // 61440

// ---- GEMM2 (fp16, 128x128 tile, ksplit 2) ----
#define T2_M 128
#define T2_N 128
#define CK 32
#define PAH 40                        // halves per smem row (80 B)
#define A_ST  (T2_M * PAH * 2)        // 10240 B per A stage
#define B_ST  (T2_N * PAH * 2)        // 10240 B per B stage
#define B_OFF (2 * A_ST)              // 2 A stages
#define RS_OFF (B_OFF + 6 * B_ST)     // 6 B stages -> 81920
#define T2_SMEM (RS_OFF + 128 * 4)    // 82432 -> 2 CTAs/SM

__device__ __align__(1024) __half g_Xh[(size_t)N_ROWS * F_IN];
__device__ __align__(1024) __half g_Wth[(size_t)F_OUT * F_IN];
__device__ __align__(1024) __half g_Yt[(size_t)F_OUT * N_ROWS];
__device__ __align__(1024) float  g_Part[2ull * N_ROWS * F_OUT];   // 16 MB partials
__device__ __align__(1024) float  g_RSp[2ull * N_ROWS];            // partial rowsums

// ---------------- device helpers ----------------
__device__ __forceinline__ uint32_t pack_h2(float lo, float hi) {
    uint32_t u;
    asm("cvt.rn.f16x2.f32 %0, %1, %2;" : "=r"(u) : "f"(hi), "f"(lo));
    return u;
}
__device__ __forceinline__ void mma_f16_k16(float* c, const uint32_t* a, const uint32_t* b) {
    asm volatile(
        "mma.sync.aligned.m16n8k16.row.col.f32.f16.f16.f32 "
        "{%0,%1,%2,%3}, {%4,%5,%6,%7}, {%8,%9}, {%0,%1,%2,%3};"
        : "+f"(c[0]), "+f"(c[1]), "+f"(c[2]), "+f"(c[3])
        : "r"(a[0]), "r"(a[1]), "r"(a[2]), "r"(a[3]), "r"(b[0]), "r"(b[1]));
}
__device__ __forceinline__ void cpa16(uint32_t s, const void* g) {
    asm volatile("cp.async.cg.shared.global [%0], [%1], 16;" :: "r"(s), "l"(g));
}
__device__ __forceinline__ void ldsm4(uint32_t& r0, uint32_t& r1, uint32_t& r2, uint32_t& r3,
                                      uint32_t addr) {
    asm volatile("ldmatrix.sync.aligned.m8n8.x4.shared.b16 {%0,%1,%2,%3}, [%4];"
                 : "=r"(r0), "=r"(r1), "=r"(r2), "=r"(r3) : "r"(addr));
}
__device__ __forceinline__ uint32_t smem_u32(const void* p) {
    uint32_t a;
    asm("{ .reg .u64 t; cvta.to.shared.u64 t, %1; cvt.u32.u64 %0, t; }" : "=r"(a) : "l"(p));
    return a;
}

// ---------------- prep kernels ----------------
__global__ void __launch_bounds__(256, 1) prep_xh(const float* __restrict__ x,
                                                  __half* __restrict__ xh) {
    int i = blockIdx.x * 256 + threadIdx.x;
    float4 v = reinterpret_cast<const float4*>(x)[i];
    uint2 o;
    o.x = pack_h2(v.x, v.y);
    o.y = pack_h2(v.z, v.w);
    reinterpret_cast<uint2*>(xh)[i] = o;
}
__global__ void __launch_bounds__(256, 1) prep_wh(const float* __restrict__ w,
                                                  __half* __restrict__ wth) {
    int t = blockIdx.x * 256 + threadIdx.x;
    int fi = t & 511, fo = t >> 9;
    wth[t] = __float2half_rn(w[fi * F_OUT + fo]);
}

// ---------------- GEMM1 (fp16): Yt[256,8192] = Wth @ Xh^T ----------------
__global__ void __launch_bounds__(256, 1) gemm1_f16(
    const __half* __restrict__ P, const __half* __restrict__ Q,
    __half* __restrict__ out)
{
    extern __shared__ char smem[];
    const uint32_t sbase = smem_u32(smem);

    const int tid  = threadIdx.x;
    const int lane = tid & 31;
    const int wid  = tid >> 5;
    const int gid  = lane >> 2;
    const int tig  = lane & 3;
    const int wm   = wid >> 1;
    const int wn   = wid & 1;
    const int lrow = lane & 15;
    const int lhi  = (lane >> 4) & 1;

    const int mtile = blockIdx.x >> 6;
    const int ntile = blockIdx.x & 63;
    const int m0 = mtile * 128;
    const int n0 = ntile * 128;
    const int kchunks = F_IN / CK;

    const int rw = tid >> 2;
    const int sg = tid & 3;
    const __half* gA = P + (size_t)(m0 + rw) * F_IN + sg * 8;
    const __half* gB = Q + (size_t)(n0 + rw) * F_IN + sg * 8;

    auto issue = [&](int kc, int s) {
        uint32_t sA = sbase + s * G1_STAGE + rw * 80 + sg * 16;
        uint32_t sB = sA + G1_ST;
        cpa16(sA,           gA + kc * CK);
        cpa16(sA + 64 * 80, gA + kc * CK + (size_t)64 * F_IN);
        cpa16(sB,           gB + kc * CK);
        cpa16(sB + 64 * 80, gB + kc * CK + (size_t)64 * F_IN);
        asm volatile("cp.async.commit_group;" ::: "memory");
    };

    float acc[2][8][4];
    #pragma unroll
    for (int mi = 0; mi < 2; mi++)
        #pragma unroll
        for (int ni = 0; ni < 8; ni++)
            #pragma unroll
            for (int i = 0; i < 4; i++) acc[mi][ni][i] = 0.f;

    issue(0, 0);
    issue(1, 1);

    int s_c = 0, s_p = 2;
    for (int kc = 0; kc < kchunks; kc++) {
        asm volatile("cp.async.wait_group %0;" :: "n"(1) : "memory");
        __syncthreads();
        const uint32_t aBase = sbase + s_c * G1_STAGE;
        const uint32_t bBase = aBase + G1_ST;

        #pragma unroll
        for (int ks = 0; ks < 2; ks++) {
            uint32_t af[2][4], bf[8][2];
            #pragma unroll
            for (int mi = 0; mi < 2; mi++) {
                uint32_t ad = aBase + ((wm * 32 + mi * 16 + lrow) * PAH + ks * 16 + lhi * 8) * 2;
                ldsm4(af[mi][0], af[mi][1], af[mi][2], af[mi][3], ad);
            }
            #pragma unroll
            for (int np = 0; np < 4; np++) {
                uint32_t bd = bBase + ((wn * 64 + np * 16 + lrow) * PAH + ks * 16 + lhi * 8) * 2;
                uint32_t r0, r1, r2, r3;
                ldsm4(r0, r1, r2, r3, bd);
                bf[np * 2 + 0][0] = r0; bf[np * 2 + 0][1] = r2;
                bf[np * 2 + 1][0] = r1; bf[np * 2 + 1][1] = r3;
            }
            #pragma unroll
            for (int mi = 0; mi < 2; mi++)
                #pragma unroll
                for (int ni = 0; ni < 8; ni++)
                    mma_f16_k16(acc[mi][ni], af[mi], bf[ni]);
        }

        if (kc + 2 < kchunks) issue(kc + 2, s_p);
        else asm volatile("cp.async.commit_group;" ::: "memory");
        if (++s_c == 3) s_c = 0;
        if (++s_p == 3) s_p = 0;
    }

    #pragma unroll
    for (int mi = 0; mi < 2; mi++) {
        const int r0 = m0 + wm * 32 + mi * 16 + gid;
        #pragma unroll
        for (int ni = 0; ni < 8; ni++) {
            const int cg = n0 + wn * 64 + ni * 8 + tig * 2;
            *(uint32_t*)(out + (size_t)r0 * N_ROWS + cg) =
                pack_h2(acc[mi][ni][0], acc[mi][ni][1]);
            *(uint32_t*)(out + (size_t)(r0 + 8) * N_ROWS + cg) =
                pack_h2(acc[mi][ni][2], acc[mi][ni][3]);
        }
    }
}

// ---------------- GEMM2 (fp16, 128x128, ksplit): partials + partial rowsums --------
__global__ void __launch_bounds__(256, 2) gemm2_f16(
    const float* __restrict__ A, const __half* __restrict__ Yt,
    float* __restrict__ part, float* __restrict__ rsp)
{
    extern __shared__ char smem[];
    const uint32_t sbase = smem_u32(smem);

    const int tid  = threadIdx.x;
    const int lane = tid & 31;
    const int wid  = tid >> 5;
    const int gid  = lane >> 2;
    const int tig  = lane & 3;
    const int wm   = wid >> 1;            // 0..3 (M strips of 32)
    const int wn   = wid & 1;             // 0..1 (N strips of 64)
    const int lrow = lane & 15;
    const int lhi  = (lane >> 4) & 1;

    const int mtile = blockIdx.x >> 2;            // 0..63
    const int ntile = (blockIdx.x >> 1) & 1;      // 0..1
    const int ks    = blockIdx.x & 1;             // 0..1 (K split)
    const int m0 = mtile * T2_M;
    const int n0 = ntile * T2_N;
    const int kchunks = 128;                      // half of 8192/32

    // producer mappings
    const int ra = tid >> 3;              // 0..31  (A row mod 32)
    const int sa = tid & 7;               // 0..7   (A 16B segment)
    const int rb = tid >> 2;              // 0..63  (B row mod 64)
    const int sb = tid & 3;               // 0..3   (B 16B segment)
    const float*  gA = A  + (size_t)(m0 + ra) * N_ROWS + (size_t)ks * 4096 + sa * 4;
    const __half* gB = Yt + (size_t)(n0 + rb) * N_ROWS + (size_t)ks * 4096 + sb * 8;

    float acc[2][8][4];
    #pragma unroll
    for (int mi = 0; mi < 2; mi++)
        #pragma unroll
        for (int ni = 0; ni < 8; ni++)
            #pragma unroll
            for (int i = 0; i < 4; i++) acc[mi][ni][i] = 0.f;
    float rsum[4] = {0.f, 0.f, 0.f, 0.f};

    auto issueB = [&](int kc, int s6) {
        if (kc < kchunks) {
            uint32_t sB = sbase + B_OFF + s6 * B_ST + rb * (PAH * 2) + sb * 16;
            cpa16(sB,                        gB + (size_t)kc * CK);
            cpa16(sB + 64 * (PAH * 2),       gB + (size_t)64 * N_ROWS + (size_t)kc * CK);
        }
        asm volatile("cp.async.commit_group;" ::: "memory");
    };
    auto ldA = [&](int kc, float4* v) {
        #pragma unroll
        for (int i = 0; i < 4; i++)
            v[i] = *(const float4*)(gA + (size_t)i * 32 * N_ROWS + (size_t)kc * CK);
    };
    auto stA = [&](int kc, const float4* v) {
        const uint32_t aw = sbase + (kc & 1) * A_ST + ra * (PAH * 2) + sa * 8;
        #pragma unroll
        for (int i = 0; i < 4; i++) {
            uint32_t h01 = pack_h2(v[i].x, v[i].y);
            uint32_t h23 = pack_h2(v[i].z, v[i].w);
            asm volatile("st.shared.v2.b32 [%0], {%1,%2};"
                         :: "r"(aw + i * 32 * (PAH * 2)), "r"(h01), "r"(h23));
            rsum[i] += (v[i].x + v[i].y) + (v[i].z + v[i].w);
        }
    };

    // prologue
    float4 vA[4];
    ldA(0, vA);
    issueB(0, 0);
    issueB(1, 1);
    issueB(2, 2);
    issueB(3, 3);

    int s6c = 0, s6p = 4;
    for (int kc = 0; kc < kchunks; kc++) {
        asm volatile("cp.async.wait_group %0;" :: "n"(3) : "memory");

        stA(kc, vA);
        const int kn = (kc + 1 < kchunks) ? kc + 1 : kchunks - 1;
        ldA(kn, vA);

        __syncthreads();

        issueB(kc + 4, s6p);

        // MMA over this chunk
        const uint32_t aBase = sbase + (kc & 1) * A_ST;
        const uint32_t bBase = sbase + B_OFF + s6c * B_ST;
        #pragma unroll
        for (int kh = 0; kh < 2; kh++) {
            uint32_t af[2][4], bf[8][2];
            #pragma unroll
            for (int mi = 0; mi < 2; mi++) {
                uint32_t ad = aBase + ((wm * 32 + mi * 16 + lrow) * PAH + kh * 16 + lhi * 8) * 2;
                ldsm4(af[mi][0], af[mi][1], af[mi][2], af[mi][3], ad);
            }
            #pragma unroll
            for (int np = 0; np < 4; np++) {
                uint32_t bd = bBase + ((wn * 64 + np * 16 + lrow) * PAH + kh * 16 + lhi * 8) * 2;
                uint32_t r0, r1, r2, r3;
                ldsm4(r0, r1, r2, r3, bd);
                bf[np * 2 + 0][0] = r0; bf[np * 2 + 0][1] = r2;
                bf[np * 2 + 1][0] = r1; bf[np * 2 + 1][1] = r3;
            }
            #pragma unroll
            for (int mi = 0; mi < 2; mi++)
                #pragma unroll
                for (int ni = 0; ni < 8; ni++)
                    mma_f16_k16(acc[mi][ni], af[mi], bf[ni]);
        }

        if (++s6c == 6) s6c = 0;
        if (++s6p == 6) s6p = 0;
    }

    // partial rowsum (only ntile 0 stores; identical in ntile 1)
    #pragma unroll
    for (int i = 0; i < 4; i++) {
        rsum[i] += __shfl_down_sync(0xffffffffu, rsum[i], 4, 8);
        rsum[i] += __shfl_down_sync(0xffffffffu, rsum[i], 2, 8);
        rsum[i] += __shfl_down_sync(0xffffffffu, rsum[i], 1, 8);
    }
    if (ntile == 0 && sa == 0) {
        #pragma unroll
        for (int i = 0; i < 4; i++)
            rsp[(size_t)ks * N_ROWS + m0 + i * 32 + ra] = rsum[i];
    }

    // store raw partials
    float* pout = part + (size_t)ks * N_ROWS * F_OUT;
    #pragma unroll
    for (int mi = 0; mi < 2; mi++) {
        const int r0 = m0 + wm * 32 + mi * 16 + gid;
        #pragma unroll
        for (int ni = 0; ni < 8; ni++) {
            const int cg = n0 + wn * 64 + ni * 8 + tig * 2;
            float2 v0, v1;
            v0.x = acc[mi][ni][0]; v0.y = acc[mi][ni][1];
            v1.x = acc[mi][ni][2]; v1.y = acc[mi][ni][3];
            *(float2*)(pout + (size_t)r0 * F_OUT + cg) = v0;
            *(float2*)(pout + (size_t)(r0 + 8) * F_OUT + cg) = v1;
        }
    }
}

// ---------------- reduce: out = (p0+p1)/(rs0+rs1) + bias ----------------
__global__ void __launch_bounds__(256, 4) reduce_out(
    const float* __restrict__ part, const float* __restrict__ rsp,
    const float* __restrict__ bias, float* __restrict__ out)
{
    int idx = blockIdx.x * 256 + threadIdx.x;     // over float4s: 8192*64
    int row = idx >> 6;
    int c4 = idx & 63;
    float inv = 1.f / fmaxf(rsp[row] + rsp[N_ROWS + row], 1e-12f);
    float4 p0 = reinterpret_cast<const float4*>(part)[idx];
    float4 p1 = reinterpret_cast<const float4*>(part)[idx + N_ROWS * (F_OUT / 4)];
    float4 bv = reinterpret_cast<const float4*>(bias)[c4];
    float4 o;
    o.x = (p0.x + p1.x) * inv + bv.x;
    o.y = (p0.y + p1.y) * inv + bv.y;
    o.z = (p0.z + p1.z) * inv + bv.z;
    o.w = (p0.w + p1.w) * inv + bv.w;
    reinterpret_cast<float4*>(out)[idx] = o;
}

// ---------------- host ----------------
extern "C" void kernel_launch(void* const* d_in, const int* in_sizes, int n_in,
                              void* d_out, int out_size) {
    const float *A = nullptr, *X = nullptr, *W = nullptr, *Bi = nullptr;
    for (int i = 0; i < n_in; i++) {
        long s = in_sizes[i];
        if (s == (long)N_ROWS * N_ROWS)      A  = (const float*)d_in[i];
        else if (s == (long)N_ROWS * F_IN)   X  = (const float*)d_in[i];
        else if (s == (long)F_IN * F_OUT)    W  = (const float*)d_in[i];
        else if (s == (long)F_OUT)           Bi = (const float*)d_in[i];
    }

    void *xh = nullptr, *wth = nullptr, *yt = nullptr, *pt = nullptr, *rs = nullptr;
    cudaGetSymbolAddress(&xh, g_Xh);
    cudaGetSymbolAddress(&wth, g_Wth);
    cudaGetSymbolAddress(&yt, g_Yt);
    cudaGetSymbolAddress(&pt, g_Part);
    cudaGetSymbolAddress(&rs, g_RSp);

    cudaFuncSetAttribute(gemm1_f16, cudaFuncAttributeMaxDynamicSharedMemorySize, G1_SMEM);
    cudaFuncSetAttribute(gemm2_f16, cudaFuncAttributeMaxDynamicSharedMemorySize, T2_SMEM);

    prep_xh<<<(N_ROWS * F_IN / 4) / 256, 256>>>(X, (__half*)xh);
    prep_wh<<<(F_IN * F_OUT) / 256, 256>>>(W, (__half*)wth);

    // GEMM1: Yt[256,8192] = Wth @ Xh^T
    gemm1_f16<<<2 * 64, 256, G1_SMEM>>>((const __half*)wth, (const __half*)xh, (__half*)yt);

    // GEMM2: partials (64 mtiles x 2 ntiles x 2 ksplits = 256 CTAs)
    gemm2_f16<<<64 * 2 * 2, 256, T2_SMEM>>>(A, (const __half*)yt, (float*)pt, (float*)rs);

    // reduce: out = (p0+p1)/(rs0+rs1) + bias
    reduce_out<<<(N_ROWS * F_OUT / 4) / 256, 256>>>((const float*)pt, (const float*)rs,
                                                    Bi, (float*)d_out);
}